// round 15
// baseline (speedup 1.0000x reference)
#include <cuda_runtime.h>
#include <cuda_fp16.h>
#include <cstdint>

#define BATCH 512
#define IDIM 256
#define ODIM 256
#define CDIM 128
#define HDIM 128
#define IO (IDIM * ODIM)        // 65536
#define W2COLS (IO + ODIM)      // 65792
#define KTOT (HDIM * IDIM)      // 32768
#define KE 384                  // extended K: 256 (x/base) + 128 (h/biascols)
#define NSLICES 37              // 36 x (14 main BK64) + 1 x (8 main + 6 ext)
#define BM 256
#define BN 128
#define BK 64
#define NST 14                  // stages per slice (uniform)

// ------------------------- device scratch (no allocs) -----------------------
__device__ __half g_X[(size_t)BATCH * IDIM];                // 256 KB, [b][i]
__device__ __half g_H[(size_t)129 * BATCH];                 // [hh][b]; row 128 = 1.0
__device__ __half g_W[(size_t)KTOT * ODIM];                 // 16 MB, [k][o]
__device__ __half g_Zext[(size_t)BATCH * KE];
__device__ __half g_Wext[(size_t)KE * ODIM];                // [k][o]
__device__ float g_part[(size_t)NSLICES * BATCH * ODIM];

// ------------------------- PTX helpers --------------------------------------
__device__ __forceinline__ uint32_t smem_u32(const void* p) {
    uint32_t a;
    asm("{ .reg .u64 t; cvta.to.shared.u64 t, %1; cvt.u32.u64 %0, t; }"
        : "=r"(a) : "l"(p));
    return a;
}
__device__ __forceinline__ void cp16(uint32_t s, const void* g) {
    asm volatile("cp.async.cg.shared.global [%0], [%1], 16;" :: "r"(s), "l"(g));
}
#define CP_COMMIT() asm volatile("cp.async.commit_group;" ::: "memory")
#define CP_WAIT(n)  asm volatile("cp.async.wait_group %0;" :: "n"(n) : "memory")

#define LDSM4(r0, r1, r2, r3, addr) \
    asm volatile("ldmatrix.sync.aligned.m8n8.x4.shared.b16 {%0,%1,%2,%3}, [%4];" \
        : "=r"(r0), "=r"(r1), "=r"(r2), "=r"(r3) : "r"(addr))

#define LDSM4T(r0, r1, r2, r3, addr) \
    asm volatile("ldmatrix.sync.aligned.m8n8.x4.trans.shared.b16 {%0,%1,%2,%3}, [%4];" \
        : "=r"(r0), "=r"(r1), "=r"(r2), "=r"(r3) : "r"(addr))

#define MMA16816(c, a, b0, b1) \
    asm volatile("mma.sync.aligned.m16n8k16.row.col.f32.f16.f16.f32 " \
        "{%0,%1,%2,%3}, {%4,%5,%6,%7}, {%8,%9}, {%0,%1,%2,%3};" \
        : "+f"((c)[0]), "+f"((c)[1]), "+f"((c)[2]), "+f"((c)[3]) \
        : "r"((a)[0]), "r"((a)[1]), "r"((a)[2]), "r"((a)[3]), "r"(b0), "r"(b1))

#define HMUL2(d, s) asm volatile("mul.f16x2 %0, %0, %1;" : "+r"(d) : "r"(s))

// ------------------------- fused prep kernel ---------------------------------
// 518 blocks, single wave:
//   blocks [0, 512): batch-row b = bid: W-main streaming slice (2048 chunks)
//                    interleaved with the row's x/h/Zext work
//   blocks [512, 518): Wext streaming (2048 chunks each)
#define ZB 512
#define WEB 6
#define NBLK (ZB + WEB)         // 518
#define CHUNKS_PER_BLK 2048     // uint4 chunks of g_W per block

__device__ __forceinline__ void cvt_store_w(const float4& v0, const float4& v1,
                                            __half* dst_base, int u) {
    union { __half e[8]; uint4 v; } o;
    o.e[0] = __float2half_rn(v0.x); o.e[1] = __float2half_rn(v0.y);
    o.e[2] = __float2half_rn(v0.z); o.e[3] = __float2half_rn(v0.w);
    o.e[4] = __float2half_rn(v1.x); o.e[5] = __float2half_rn(v1.y);
    o.e[6] = __float2half_rn(v1.z); o.e[7] = __float2half_rn(v1.w);
    ((uint4*)dst_base)[u] = o.v;
}

__global__ void __launch_bounds__(256)
prep_all_kernel(const float* __restrict__ x,
                const float* __restrict__ cond,
                const float* __restrict__ w1,
                const float* __restrict__ b1,
                const float* __restrict__ w2,
                const float* __restrict__ baseW,
                const float* __restrict__ b2) {
    __shared__ float cs[CDIM];
    __shared__ float xs[IDIM];
    const int bid = blockIdx.x;
    const int tid = threadIdx.x;

    if (bid < ZB) {
        const int b = bid;
        // phase 1: stage this row's inputs into smem
        if (tid < CDIM) cs[tid] = cond[b * CDIM + tid];
        xs[tid] = x[b * IDIM + tid];
        // phase 2: stream 2048 W-main chunks (memory-bound; hides phase-1 lat)
        int u0 = bid * CHUNKS_PER_BLK + tid;
#pragma unroll 4
        for (int i = 0; i < 8; i++) {
            int u = u0 + i * 256;
            int j0 = u * 8;
            int k = j0 >> 8;
            size_t in = (size_t)(k >> 8) * W2COLS + (size_t)(k & 255) * 256 + (j0 & 255);
            float4 v0 = *(const float4*)(w2 + in);
            float4 v1 = *(const float4*)(w2 + in + 4);
            cvt_store_w(v0, v1, g_W, u);
        }
        // phase 3: the row's Z work
        __syncthreads();
        __half xh = __float2half_rn(xs[tid]);
        g_X[b * IDIM + tid] = xh;
        g_Zext[b * KE + tid] = xh;
        int j = tid >> 1, hf = tid & 1;
        int k0 = hf * 64;
        float a0 = hf ? 0.f : b1[j], a1 = 0.f, a2 = 0.f, a3 = 0.f;
#pragma unroll 4
        for (int k = k0; k < k0 + 64; k += 4) {
            a0 = fmaf(cs[k],     w1[(k)     * HDIM + j], a0);
            a1 = fmaf(cs[k + 1], w1[(k + 1) * HDIM + j], a1);
            a2 = fmaf(cs[k + 2], w1[(k + 2) * HDIM + j], a2);
            a3 = fmaf(cs[k + 3], w1[(k + 3) * HDIM + j], a3);
        }
        float s = (a0 + a1) + (a2 + a3);
        s += __shfl_xor_sync(0xffffffffu, s, 1);
        if (hf == 0) {
            __half hv = __float2half_rn(fmaxf(s, 0.0f));
            g_H[j * BATCH + b] = hv;
            g_Zext[b * KE + 256 + j] = hv;
        }
        if (tid == 255) g_H[128 * BATCH + b] = __float2half_rn(1.0f);
    } else {
        // ---- Wext: [k][o]; 6 blocks x 2048 chunks ----
        int u0 = (bid - ZB) * CHUNKS_PER_BLK + tid;
#pragma unroll 4
        for (int i = 0; i < 8; i++) {
            int u = u0 + i * 256;
            int j0 = u * 8;
            int k = j0 >> 8, o0 = j0 & 255;
            float4 v0, v1;
            if (k < 256) {
                float4 a0 = *(const float4*)(baseW + k * ODIM + o0);
                float4 a1 = *(const float4*)(baseW + k * ODIM + o0 + 4);
                float4 c0 = *(const float4*)(b2 + k * ODIM + o0);
                float4 c1 = *(const float4*)(b2 + k * ODIM + o0 + 4);
                v0 = make_float4(a0.x + c0.x, a0.y + c0.y, a0.z + c0.z, a0.w + c0.w);
                v1 = make_float4(a1.x + c1.x, a1.y + c1.y, a1.z + c1.z, a1.w + c1.w);
            } else {
                const float* src = w2 + (size_t)(k - 256) * W2COLS + IO + o0;
                v0 = *(const float4*)(src);
                v1 = *(const float4*)(src + 4);
            }
            cvt_store_w(v0, v1, g_Wext, u);
        }
    }
}

// ------------------------- HMMA GEMM (A on-the-fly, BK=64, 4-stage) ---------
// C = (h∘x)@W (+ ext). A-tile = x fp16 tile scaled by per-stage h in regs
// (hh constant within a BK=64 stage). BM=256 x BN=128, 256 threads (8 warps,
// 4m x 2n, warp 64x64), 4-stage cp.async pipeline. grid 2x2x37 = 148 CTAs.
#define STG_BYTES 49664          // A 32K + B 16K + h 512 + pad
#define OFF_A 0
#define OFF_B 32768
#define OFF_H 49152
#define SMEM_TOTAL (4 * STG_BYTES)   // 198656

__global__ void __launch_bounds__(256, 1)
gemm_hmma_kernel() {
    extern __shared__ char smem[];
    const uint32_t sbase = smem_u32(smem);
    const int tid = threadIdx.x;
    const int wid = tid >> 5, lane = tid & 31;
    const int n0 = blockIdx.x * BN;
    const int m0 = blockIdx.y * BM;
    const int z = blockIdx.z;
    const bool mixed = (z == NSLICES - 1);

    const int m_base = (wid >> 1) * 64;   // 4 warps along M
    const int n_base = (wid & 1) * 64;    // 2 warps along N

    auto load_stage = [&](int kt) {
        uint32_t sb = sbase + (uint32_t)(kt & 3) * STG_BYTES;
        const __half* A;
        const __half* B;
        size_t kstrA;
        int kb, hh;
        if (!mixed || kt < 8) {
            int k0 = (z * NST + kt) * BK;
            hh = k0 >> 8;
            A = g_X; kstrA = IDIM; kb = k0 & 255;
            B = g_W + (size_t)k0 * ODIM;
        } else {
            A = g_Zext; kstrA = KE; kb = (kt - 8) * BK;
            hh = 128;
            B = g_Wext + (size_t)kb * ODIM;
        }
        // A: 256 rows x 128B -> 2048 chunks, 8 per thread
#pragma unroll
        for (int i = 0; i < 8; i++) {
            int t = tid + i * 256;
            int row = t >> 3, ch = t & 7;
            uint32_t sw = (uint32_t)row * 128 + ((ch ^ (row & 7)) << 4);
            cp16(sb + OFF_A + sw, A + (size_t)(m0 + row) * kstrA + kb + ch * 8);
        }
        // B: 64 k-rows x 256B -> 1024 chunks, 4 per thread ([k][o] layout)
#pragma unroll
        for (int i = 0; i < 4; i++) {
            int t = tid + i * 256;
            int row = t >> 4, ch = t & 15;
            uint32_t sw = (uint32_t)row * 256 + ((ch ^ (row & 7)) << 4);
            cp16(sb + OFF_B + sw, B + (size_t)row * ODIM + n0 + ch * 8);
        }
        // h column for this stage's hh: 256 rows x 2B = 512B
        if (tid < 32)
            cp16(sb + OFF_H + tid * 16, g_H + hh * BATCH + m0 + tid * 8);
    };

    float acc[4][8][4];
#pragma unroll
    for (int i = 0; i < 4; i++)
#pragma unroll
        for (int j = 0; j < 8; j++)
#pragma unroll
            for (int q = 0; q < 4; q++) acc[i][j][q] = 0.0f;

    const int arow_base = m_base + (lane & 15);
    const int asel = lane >> 4;
    const int brow_lane = lane & 15;          // k-row within k16 step
    const int bch_lane = (lane >> 4) & 1;     // n8 group select
    const int hrow = m_base + (lane >> 2);    // fragment-owner row

    load_stage(0); CP_COMMIT();
    load_stage(1); CP_COMMIT();
    load_stage(2); CP_COMMIT();

    for (int kt = 0; kt < NST; kt++) {
        CP_WAIT(2);
        __syncthreads();
        if (kt + 3 < NST) load_stage(kt + 3);
        CP_COMMIT();

        uint32_t sb = sbase + (uint32_t)(kt & 3) * STG_BYTES;

        // per-stage h scalars (packed to half2) for the 4 m-fragments
        uint32_t hq[4][2];
        uint32_t hbase = sb + OFF_H + (uint32_t)hrow * 2;
#pragma unroll
        for (int mf = 0; mf < 4; mf++) {
            uint32_t t0, t1;
            asm volatile("ld.shared.u16 %0, [%1];" : "=r"(t0) : "r"(hbase + mf * 32));
            asm volatile("ld.shared.u16 %0, [%1];" : "=r"(t1) : "r"(hbase + mf * 32 + 16));
            hq[mf][0] = t0 | (t0 << 16);
            hq[mf][1] = t1 | (t1 << 16);
        }

#pragma unroll
        for (int kk = 0; kk < 4; kk++) {
            uint32_t a[4][4], bt[4][4];
#pragma unroll
            for (int mf = 0; mf < 4; mf++) {
                int row = arow_base + mf * 16;
                int ch = 2 * kk + asel;
                uint32_t ad = sb + OFF_A + row * 128 + ((ch ^ (row & 7)) << 4);
                LDSM4(a[mf][0], a[mf][1], a[mf][2], a[mf][3], ad);
                HMUL2(a[mf][0], hq[mf][0]);
                HMUL2(a[mf][2], hq[mf][0]);
                HMUL2(a[mf][1], hq[mf][1]);
                HMUL2(a[mf][3], hq[mf][1]);
            }
#pragma unroll
            for (int np = 0; np < 4; np++) {
                int row = kk * 16 + brow_lane;
                int ch = (n_base >> 3) + np * 2 + bch_lane;
                uint32_t bd = sb + OFF_B + row * 256 + ((ch ^ (row & 7)) << 4);
                LDSM4T(bt[np][0], bt[np][1], bt[np][2], bt[np][3], bd);
            }
#pragma unroll
            for (int mf = 0; mf < 4; mf++)
#pragma unroll
                for (int np = 0; np < 4; np++) {
                    MMA16816(acc[mf][2 * np], a[mf], bt[np][0], bt[np][1]);
                    MMA16816(acc[mf][2 * np + 1], a[mf], bt[np][2], bt[np][3]);
                }
        }
    }
    CP_WAIT(0);

    float* dst = g_part + (size_t)z * (BATCH * ODIM);
#pragma unroll
    for (int mf = 0; mf < 4; mf++) {
#pragma unroll
        for (int nf = 0; nf < 8; nf++) {
            int m = m0 + m_base + mf * 16 + (lane >> 2);
            int o = n0 + n_base + nf * 8 + (lane & 3) * 2;
            float2 v0 = make_float2(acc[mf][nf][0], acc[mf][nf][1]);
            float2 v1 = make_float2(acc[mf][nf][2], acc[mf][nf][3]);
            *(float2*)(dst + (size_t)m * ODIM + o) = v0;
            *(float2*)(dst + (size_t)(m + 8) * ODIM + o) = v1;
        }
    }
}

// ------------------------- split-K reduction + bias --------------------------
__global__ void reduce_kernel(const float* __restrict__ base_bias,
                              const float* __restrict__ b2,
                              float* __restrict__ out) {
    int b = blockIdx.x, o = threadIdx.x;
    float acc = base_bias[o] + b2[IO + o];
#pragma unroll
    for (int s = 0; s < NSLICES; s++)
        acc += g_part[((size_t)s * BATCH + b) * ODIM + o];
    out[b * ODIM + o] = acc;
}

// ------------------------- launcher -----------------------------------------
extern "C" void kernel_launch(void* const* d_in, const int* in_sizes, int n_in,
                              void* d_out, int out_size) {
    const float* x    = (const float*)d_in[0];
    const float* cond = (const float*)d_in[1];
    const float* bw   = (const float*)d_in[2];
    const float* bb   = (const float*)d_in[3];
    const float* w1   = (const float*)d_in[4];
    const float* b1   = (const float*)d_in[5];
    const float* w2   = (const float*)d_in[6];
    const float* b2   = (const float*)d_in[7];
    float* out = (float*)d_out;

    cudaFuncSetAttribute(gemm_hmma_kernel,
                         cudaFuncAttributeMaxDynamicSharedMemorySize, SMEM_TOTAL);

    prep_all_kernel<<<NBLK, 256>>>(x, cond, w1, b1, w2, bw, b2);
    gemm_hmma_kernel<<<dim3(ODIM / BN, BATCH / BM, NSLICES), 256, SMEM_TOTAL>>>();
    reduce_kernel<<<BATCH, 256>>>(bb, b2, out);
}